// round 14
// baseline (speedup 1.0000x reference)
#include <cuda_runtime.h>
#include <cuda_fp16.h>
#include <cstdint>

#define N_NODES 100000
#define N_EDGES 1600000
#define IN_CH   128
#define HID_CH  64
#define OUT_CH  32
#define GEMM_ROWS 128
#define N_GEMM_BLK ((N_NODES + GEMM_ROWS - 1) / GEMM_ROWS)    // 782

// persistent preprocessing kernel: one CTA per SM (residency guaranteed)
#define PRE_BLKS 148
#define PRE_THR  512
#define PRE_STRIDE (PRE_BLKS * PRE_THR)
#define CHUNK ((N_NODES + PRE_BLKS - 1) / PRE_BLKS)          // 676

typedef unsigned long long u64;

#define FMA_X2(d, a, b) \
    asm("fma.rn.f32x2 %0, %1, %2, %0;" : "+l"(d) : "l"(a), "l"(b))
#define DUP_X2(out, f) \
    asm("mov.b64 %0, {%1, %1};" : "=l"(out) : "f"(f))
#define UNPK_X2(lo, hi, in) \
    asm("mov.b64 {%0, %1}, %2;" : "=f"(lo), "=f"(hi) : "l"(in))

#define CP_ASYNC16(saddr, gptr) \
    asm volatile("cp.async.ca.shared.global [%0], [%1], 16;" :: "r"(saddr), "l"(gptr) : "memory")
#define CP_ASYNC_COMMIT() asm volatile("cp.async.commit_group;" ::: "memory")
#define CP_ASYNC_WAIT0()  asm volatile("cp.async.wait_group 0;" ::: "memory")

__device__ __forceinline__ uint32_t smem_u32(const void* p) {
    uint32_t a;
    asm("{ .reg .u64 t; cvta.to.shared.u64 t, %1; cvt.u32.u64 %0, t; }" : "=r"(a) : "l"(p));
    return a;
}

// ---------------- scratch ----------------
__device__ int     g_cnt [N_NODES];
__device__ int     g_inc [N_NODES];
__device__ int     g_bsum[PRE_BLKS];
__device__ int     g_off [N_NODES + 1];
__device__ int     g_cur [N_NODES];
__device__ float   g_dinv[N_NODES];
__device__ int     g_csr [N_EDGES];                         // src*(HID_CH/2), grouped by dst
__device__ __half2 g_f1h [(size_t)N_NODES * (HID_CH / 2)];  // fp16(x@W1 * dinv[row])
__device__ float   g_r1  [(size_t)N_NODES * HID_CH];        // fp32 relu(agg1)
__device__ __half  g_f2h [(size_t)N_NODES * OUT_CH];        // fp16(r1@W2 * dinv[row])
__device__ int     g_idx64;

// ---------------- grid barrier (all PRE_BLKS CTAs resident) ----------------
__device__ int          g_sync_cnt;
__device__ volatile int g_sync_gen;

__device__ __forceinline__ void grid_sync() {
    __syncthreads();
    if (threadIdx.x == 0) {
        int gen = g_sync_gen;
        __threadfence();
        if (atomicAdd(&g_sync_cnt, 1) == PRE_BLKS - 1) {
            g_sync_cnt = 0;
            __threadfence();
            g_sync_gen = gen + 1;
        } else {
            while (g_sync_gen == gen) { }
        }
    }
    __syncthreads();
}

__device__ __forceinline__ int load_id(const void* ei, int idx) {
    if (g_idx64) return (int)((const long long*)ei)[idx];
    return ((const int*)ei)[idx];
}

__device__ __forceinline__ int warp_iscan(int v, int lane) {
    #pragma unroll
    for (int o = 1; o < 32; o <<= 1) {
        int u = __shfl_up_sync(0xffffffffu, v, o);
        if (lane >= o) v += u;
    }
    return v;
}

// ---------------- fused preprocessing (R9 config): zero+detect | hist | scan | finalize | fill ----------------
__global__ void __launch_bounds__(PRE_THR) k_preproc(const void* __restrict__ ei, int n_elems) {
    int tid  = threadIdx.x, b = blockIdx.x;
    int gtid = b * PRE_THR + tid;

    // P0: zero histogram + dtype detect (block 0)
    for (int i = gtid; i < N_NODES; i += PRE_STRIDE) g_cnt[i] = 0;
    if (b == 0) {
        __shared__ int bad;
        if (tid == 0) bad = 0;
        __syncthreads();
        const long long* p = (const long long*)ei;
        long long m = (long long)n_elems / 2;
        if (m > 2048) m = 2048;
        for (int j = tid; j < m; j += PRE_THR) {
            long long v = p[j];
            if (v < 0 || v >= N_NODES) bad = 1;
        }
        __syncthreads();
        if (tid == 0) g_idx64 = bad ? 0 : 1;
    }
    grid_sync();

    // P1: in-degree histogram
    for (int e = gtid; e < N_EDGES; e += PRE_STRIDE)
        atomicAdd(&g_cnt[load_id(ei, N_EDGES + e)], 1);
    grid_sync();

    // P2: per-block scan of contiguous chunk (2 elems/thread)
    {
        int base = b * CHUNK;
        int lane = tid & 31, w = tid >> 5;
        __shared__ int ws[PRE_THR / 32];
        int i0 = base + 2 * tid, i1 = i0 + 1;
        bool p0 = (2 * tid < CHUNK) && (i0 < N_NODES);
        bool p1 = (2 * tid + 1 < CHUNK) && (i1 < N_NODES);
        int v0 = p0 ? g_cnt[i0] : 0;
        int v1 = p1 ? g_cnt[i1] : 0;
        int s = warp_iscan(v0 + v1, lane);
        if (lane == 31) ws[w] = s;
        __syncthreads();
        if (tid == 0) {
            int a = 0;
            #pragma unroll
            for (int k = 0; k < PRE_THR / 32; k++) { a += ws[k]; ws[k] = a; }
        }
        __syncthreads();
        int sincl = s + (w > 0 ? ws[w - 1] : 0);
        if (p0) g_inc[i0] = sincl - v1;
        if (p1) g_inc[i1] = sincl;
        if (tid == 0) g_bsum[b] = ws[PRE_THR / 32 - 1];
    }
    grid_sync();

    // P3: block prefix from bsum + finalize offsets/cursors/dinv
    {
        __shared__ int pfx;
        if (tid < 32) {
            int sacc = 0;
            for (int i = tid; i < b; i += 32) sacc += g_bsum[i];
            #pragma unroll
            for (int o = 16; o; o >>= 1) sacc += __shfl_down_sync(0xffffffffu, sacc, o);
            if (tid == 0) pfx = sacc;
        }
        __syncthreads();
        int base = b * CHUNK;
        for (int k = tid; k < CHUNK; k += PRE_THR) {
            int i = base + k;
            if (i < N_NODES) {
                int c = g_cnt[i];
                int off = g_inc[i] - c + pfx;
                g_off[i] = off;
                g_cur[i] = off;
                g_dinv[i] = rsqrtf((float)c + 1.0f);
            }
        }
        if (b == 0 && tid == 0) g_off[N_NODES] = N_EDGES;
    }
    grid_sync();

    // P4: CSR bucket fill (edge list still L2-resident from P1)
    for (int e = gtid; e < N_EDGES; e += PRE_STRIDE) {
        int s = load_id(ei, e);
        int d = load_id(ei, N_EDGES + e);
        int pos = atomicAdd(&g_cur[d], 1);
        g_csr[pos] = s * (HID_CH / 2);
    }
}

// ---------------- GEMM1: f1h = fp16((x @ W1) * dinv[row]) ----------------
__global__ void __launch_bounds__(256) k_gemm1(const float* __restrict__ x,
                                               const float* __restrict__ W1) {
    __shared__ float Ws[IN_CH * HID_CH];   // 32KB
    int tid = threadIdx.x;
    {
        const float4* W4 = (const float4*)W1;
        float4* Ws4 = (float4*)Ws;
        #pragma unroll
        for (int i = 0; i < (IN_CH * HID_CH / 4) / 256; i++)
            Ws4[tid + 256 * i] = W4[tid + 256 * i];
    }
    __syncthreads();

    int t    = tid & 7;
    int row0 = blockIdx.x * GEMM_ROWS + (tid >> 3) * 4;
    bool v0 = row0     < N_NODES, v1 = row0 + 1 < N_NODES;
    bool v2 = row0 + 2 < N_NODES, v3 = row0 + 3 < N_NODES;

    u64 acc[4][4];
    #pragma unroll
    for (int r = 0; r < 4; r++)
        #pragma unroll
        for (int j = 0; j < 4; j++) acc[r][j] = 0ull;

    const float4* xr = (const float4*)(x + (size_t)row0 * IN_CH);
    const float4 z4 = make_float4(0.f, 0.f, 0.f, 0.f);

    #pragma unroll 4
    for (int k4 = 0; k4 < IN_CH / 4; k4++) {
        float4 xa0 = v0 ? xr[k4]                    : z4;
        float4 xa1 = v1 ? xr[k4 + IN_CH / 4]        : z4;
        float4 xa2 = v2 ? xr[k4 + 2 * (IN_CH / 4)]  : z4;
        float4 xa3 = v3 ? xr[k4 + 3 * (IN_CH / 4)]  : z4;
        #pragma unroll
        for (int dk = 0; dk < 4; dk++) {
            float s0 = (dk == 0) ? xa0.x : (dk == 1) ? xa0.y : (dk == 2) ? xa0.z : xa0.w;
            float s1 = (dk == 0) ? xa1.x : (dk == 1) ? xa1.y : (dk == 2) ? xa1.z : xa1.w;
            float s2 = (dk == 0) ? xa2.x : (dk == 1) ? xa2.y : (dk == 2) ? xa2.z : xa2.w;
            float s3 = (dk == 0) ? xa3.x : (dk == 1) ? xa3.y : (dk == 2) ? xa3.z : xa3.w;
            u64 xp[4];
            DUP_X2(xp[0], s0); DUP_X2(xp[1], s1);
            DUP_X2(xp[2], s2); DUP_X2(xp[3], s3);
            const u64* wr = (const u64*)&Ws[(k4 * 4 + dk) * HID_CH + t * 8];
            u64 w0 = wr[0], w1 = wr[1], w2 = wr[2], w3 = wr[3];
            #pragma unroll
            for (int r = 0; r < 4; r++) {
                FMA_X2(acc[r][0], xp[r], w0);
                FMA_X2(acc[r][1], xp[r], w1);
                FMA_X2(acc[r][2], xp[r], w2);
                FMA_X2(acc[r][3], xp[r], w3);
            }
        }
    }

    #pragma unroll
    for (int r = 0; r < 4; r++) {
        int row = row0 + r;
        if (row >= N_NODES) break;
        float di = g_dinv[row];
        float a0, a1, a2, a3, a4, a5, a6, a7;
        UNPK_X2(a0, a1, acc[r][0]); UNPK_X2(a2, a3, acc[r][1]);
        UNPK_X2(a4, a5, acc[r][2]); UNPK_X2(a6, a7, acc[r][3]);
        __half2 h0 = __floats2half2_rn(a0 * di, a1 * di);
        __half2 h1 = __floats2half2_rn(a2 * di, a3 * di);
        __half2 h2 = __floats2half2_rn(a4 * di, a5 * di);
        __half2 h3 = __floats2half2_rn(a6 * di, a7 * di);
        uint4 pk = make_uint4(*(uint32_t*)&h0, *(uint32_t*)&h1,
                              *(uint32_t*)&h2, *(uint32_t*)&h3);
        *((uint4*)(g_f1h + (size_t)row * (HID_CH / 2)) + t) = pk;
    }
}

// ---------------- agg layer 1: gather-sum (MLP 8) + self + bias + relu -> r1 fp32 ----------------
__global__ void __launch_bounds__(256) k_agg1(const float* __restrict__ b1) {
    int n = (blockIdx.x * 256 + threadIdx.x) >> 5;
    int lane = threadIdx.x & 31;
    int beg = g_off[n], end = g_off[n + 1];

    float ax = 0.f, ay = 0.f;
    int e = beg;
    while (e < end && (e & 3)) {   // peel to 16B-aligned int4 record loads
        float2 v = __half22float2(g_f1h[g_csr[e] + lane]);
        ax += v.x; ay += v.y;
        e++;
    }
    for (; e + 8 <= end; e += 8) {
        int4 Ra = *(const int4*)(g_csr + e);
        int4 Rb = *(const int4*)(g_csr + e + 4);
        float2 v0 = __half22float2(g_f1h[Ra.x + lane]);
        float2 v1 = __half22float2(g_f1h[Ra.y + lane]);
        float2 v2 = __half22float2(g_f1h[Ra.z + lane]);
        float2 v3 = __half22float2(g_f1h[Ra.w + lane]);
        float2 v4 = __half22float2(g_f1h[Rb.x + lane]);
        float2 v5 = __half22float2(g_f1h[Rb.y + lane]);
        float2 v6 = __half22float2(g_f1h[Rb.z + lane]);
        float2 v7 = __half22float2(g_f1h[Rb.w + lane]);
        ax += (v0.x + v1.x) + (v2.x + v3.x) + (v4.x + v5.x) + (v6.x + v7.x);
        ay += (v0.y + v1.y) + (v2.y + v3.y) + (v4.y + v5.y) + (v6.y + v7.y);
    }
    if (e + 4 <= end) {
        int4 R = *(const int4*)(g_csr + e);
        float2 v0 = __half22float2(g_f1h[R.x + lane]);
        float2 v1 = __half22float2(g_f1h[R.y + lane]);
        float2 v2 = __half22float2(g_f1h[R.z + lane]);
        float2 v3 = __half22float2(g_f1h[R.w + lane]);
        ax += (v0.x + v1.x) + (v2.x + v3.x);
        ay += (v0.y + v1.y) + (v2.y + v3.y);
        e += 4;
    }
    for (; e < end; e++) {
        float2 v = __half22float2(g_f1h[g_csr[e] + lane]);
        ax += v.x; ay += v.y;
    }

    float di = g_dinv[n];
    float2 self = __half22float2(g_f1h[(size_t)n * (HID_CH / 2) + lane]);
    float2 bb   = *(const float2*)(b1 + 2 * lane);
    float rx = fmaxf((ax + self.x) * di + bb.x, 0.f);
    float ry = fmaxf((ay + self.y) * di + bb.y, 0.f);
    *(float2*)(g_r1 + (size_t)n * HID_CH + 2 * lane) = make_float2(rx, ry);
}

// ---------------- GEMM2: f2h = fp16((r1 @ W2) * dinv[row]) ----------------
// r1 tile staged to smem via cp.async (no register-dependent global loads ->
// full-MLP DRAM streaming), compute entirely from smem.
__global__ void __launch_bounds__(256) k_gemm2(const float* __restrict__ W2) {
    __shared__ float Ws[HID_CH * OUT_CH];        // 8KB
    __shared__ float Xs[GEMM_ROWS * HID_CH];     // 32KB r1 tile
    int tid = threadIdx.x;
    int base_row = blockIdx.x * GEMM_ROWS;

    // stage r1 tile (32KB contiguous) via cp.async: thread copies 128B
    {
        const char* gsrc = (const char*)(g_r1 + (size_t)base_row * HID_CH);
        uint32_t sdst = smem_u32(Xs);
        long long maxb = ((long long)N_NODES - base_row) * (HID_CH * 4);
        #pragma unroll
        for (int i = 0; i < 8; i++) {
            int off = tid * 128 + i * 16;
            if (off < maxb) CP_ASYNC16(sdst + off, gsrc + off);
        }
        CP_ASYNC_COMMIT();
    }
    // W2 -> smem (overlaps with async copy)
    {
        const float4* W4 = (const float4*)W2;
        float4* Ws4 = (float4*)Ws;
        #pragma unroll
        for (int i = 0; i < (HID_CH * OUT_CH / 4) / 256; i++)
            Ws4[tid + 256 * i] = W4[tid + 256 * i];
    }
    CP_ASYNC_WAIT0();
    __syncthreads();

    int t    = tid & 7;
    int rl0  = (tid >> 3) * 4;           // local row within tile
    int row0 = base_row + rl0;

    u64 acc[4][2];
    #pragma unroll
    for (int r = 0; r < 4; r++) { acc[r][0] = 0ull; acc[r][1] = 0ull; }

    const float4* xr = (const float4*)(Xs + rl0 * HID_CH);

    #pragma unroll 4
    for (int k4 = 0; k4 < HID_CH / 4; k4++) {
        float4 xa0 = xr[k4];
        float4 xa1 = xr[k4 + HID_CH / 4];
        float4 xa2 = xr[k4 + 2 * (HID_CH / 4)];
        float4 xa3 = xr[k4 + 3 * (HID_CH / 4)];
        #pragma unroll
        for (int dk = 0; dk < 4; dk++) {
            float s0 = (dk == 0) ? xa0.x : (dk == 1) ? xa0.y : (dk == 2) ? xa0.z : xa0.w;
            float s1 = (dk == 0) ? xa1.x : (dk == 1) ? xa1.y : (dk == 2) ? xa1.z : xa1.w;
            float s2 = (dk == 0) ? xa2.x : (dk == 1) ? xa2.y : (dk == 2) ? xa2.z : xa2.w;
            float s3 = (dk == 0) ? xa3.x : (dk == 1) ? xa3.y : (dk == 2) ? xa3.z : xa3.w;
            u64 xp[4];
            DUP_X2(xp[0], s0); DUP_X2(xp[1], s1);
            DUP_X2(xp[2], s2); DUP_X2(xp[3], s3);
            const u64* wr = (const u64*)&Ws[(k4 * 4 + dk) * OUT_CH + t * 4];
            u64 w0 = wr[0], w1 = wr[1];
            #pragma unroll
            for (int r = 0; r < 4; r++) {
                FMA_X2(acc[r][0], xp[r], w0);
                FMA_X2(acc[r][1], xp[r], w1);
            }
        }
    }

    #pragma unroll
    for (int r = 0; r < 4; r++) {
        int row = row0 + r;
        if (row >= N_NODES) break;
        float di = g_dinv[row];
        float a0, a1, a2, a3;
        UNPK_X2(a0, a1, acc[r][0]); UNPK_X2(a2, a3, acc[r][1]);
        __half2 h0 = __floats2half2_rn(a0 * di, a1 * di);
        __half2 h1 = __floats2half2_rn(a2 * di, a3 * di);
        uint2 pk = make_uint2(*(uint32_t*)&h0, *(uint32_t*)&h1);
        *((uint2*)(g_f2h + (size_t)row * OUT_CH) + t) = pk;
    }
}

// ---------------- agg layer 2: half-warp edge pairing (MLP 4) ----------------
__global__ void __launch_bounds__(256) k_agg2(const float* __restrict__ b2,
                                              float* __restrict__ out) {
    int n = (blockIdx.x * 256 + threadIdx.x) >> 5;
    int lane = threadIdx.x & 31;
    int half = lane >> 4;
    int c    = lane & 15;
    int beg = g_off[n], end = g_off[n + 1];
    const __half2* f2 = (const __half2*)g_f2h;

    float ax = 0.f, ay = 0.f;
    int e = beg;
    while (e < end && (e & 3)) {
        if (half == 0) {
            float2 v = __half22float2(f2[(g_csr[e] >> 1) + c]);
            ax += v.x; ay += v.y;
        }
        e++;
    }
    for (; e + 8 <= end; e += 8) {
        int4 Ra = *(const int4*)(g_csr + e);
        int4 Rb = *(const int4*)(g_csr + e + 4);
        int r0 = half ? Ra.y : Ra.x;
        int r1 = half ? Ra.w : Ra.z;
        int r2 = half ? Rb.y : Rb.x;
        int r3 = half ? Rb.w : Rb.z;
        float2 v0 = __half22float2(f2[(r0 >> 1) + c]);
        float2 v1 = __half22float2(f2[(r1 >> 1) + c]);
        float2 v2 = __half22float2(f2[(r2 >> 1) + c]);
        float2 v3 = __half22float2(f2[(r3 >> 1) + c]);
        ax += (v0.x + v1.x) + (v2.x + v3.x);
        ay += (v0.y + v1.y) + (v2.y + v3.y);
    }
    if (e + 4 <= end) {
        int4 R = *(const int4*)(g_csr + e);
        int r0 = half ? R.y : R.x;
        int r1 = half ? R.w : R.z;
        float2 v0 = __half22float2(f2[(r0 >> 1) + c]);
        float2 v1 = __half22float2(f2[(r1 >> 1) + c]);
        ax += v0.x + v1.x;
        ay += v0.y + v1.y;
        e += 4;
    }
    for (; e + 2 <= end; e += 2) {
        float2 v = __half22float2(f2[(g_csr[e + half] >> 1) + c]);
        ax += v.x; ay += v.y;
    }
    if (e < end && half == 0) {
        float2 v = __half22float2(f2[(g_csr[e] >> 1) + c]);
        ax += v.x; ay += v.y;
    }

    ax += __shfl_xor_sync(0xffffffffu, ax, 16);
    ay += __shfl_xor_sync(0xffffffffu, ay, 16);

    if (half == 0) {
        float di = g_dinv[n];
        float2 self = __half22float2(f2[(size_t)n * (OUT_CH / 2) + c]);
        float2 bb   = *(const float2*)(b2 + 2 * c);
        *(float2*)(out + (size_t)n * OUT_CH + 2 * c) =
            make_float2((ax + self.x) * di + bb.x, (ay + self.y) * di + bb.y);
    }
}

// ---------------- launch ----------------
extern "C" void kernel_launch(void* const* d_in, const int* in_sizes, int n_in,
                              void* d_out, int out_size) {
    const float* x  = (const float*)d_in[0];
    const void*  ei = d_in[1];
    const float* W1 = (const float*)d_in[2];
    const float* b1 = (const float*)d_in[3];
    const float* W2 = (const float*)d_in[4];
    const float* b2 = (const float*)d_in[5];
    float* out = (float*)d_out;

    k_preproc<<<PRE_BLKS, PRE_THR>>>(ei, in_sizes[1]);
    k_gemm1  <<<N_GEMM_BLK, 256>>>(x, W1);
    k_agg1   <<<N_NODES / 8, 256>>>(b1);
    k_gemm2  <<<N_GEMM_BLK, 256>>>(W2);
    k_agg2   <<<N_NODES / 8, 256>>>(b2, out);
}

// round 16
// speedup vs baseline: 1.5099x; 1.5099x over previous
#include <cuda_runtime.h>
#include <cuda_fp16.h>
#include <cstdint>

#define N_NODES 100000
#define N_EDGES 1600000
#define IN_CH   128
#define HID_CH  64
#define OUT_CH  32
#define SCAN_BS 1024
#define N_SCAN_BLK ((N_NODES + SCAN_BS - 1) / SCAN_BS)   // 98
#define GEMM_ROWS 128
#define N_GEMM_BLK ((N_NODES + GEMM_ROWS - 1) / GEMM_ROWS)    // 782
#define GEMM2_ROWS 256
#define N_GEMM2_BLK ((N_NODES + GEMM2_ROWS - 1) / GEMM2_ROWS) // 391

typedef unsigned long long u64;

#define FMA_X2(d, a, b) \
    asm("fma.rn.f32x2 %0, %1, %2, %0;" : "+l"(d) : "l"(a), "l"(b))
#define DUP_X2(out, f) \
    asm("mov.b64 %0, {%1, %1};" : "=l"(out) : "f"(f))
#define UNPK_X2(lo, hi, in) \
    asm("mov.b64 {%0, %1}, %2;" : "=f"(lo), "=f"(hi) : "l"(in))

// ---------------- scratch ----------------
__device__ int     g_cnt [N_NODES];
__device__ int     g_inc [N_NODES];
__device__ int     g_bsum[N_SCAN_BLK];
__device__ int     g_off [N_NODES + 1];
__device__ int     g_cur [N_NODES];
__device__ float   g_dinv[N_NODES];
__device__ int     g_csr [N_EDGES];                         // src*(HID_CH/2), grouped by dst
__device__ __half2 g_f1h [(size_t)N_NODES * (HID_CH / 2)];  // fp16(x@W1 * dinv[row])
__device__ float   g_r1  [(size_t)N_NODES * HID_CH];        // fp32 relu(agg1)
__device__ __half  g_f2h [(size_t)N_NODES * OUT_CH];        // fp16(r1@W2 * dinv[row])
__device__ int     g_idx64;

// ---------------- dtype detect + histogram zero ----------------
__global__ void k_detect_zero(const void* ei, int n_elems) {
    int i = blockIdx.x * blockDim.x + threadIdx.x;
    if (i < N_NODES) g_cnt[i] = 0;
    if (blockIdx.x == 0) {
        __shared__ int bad;
        if (threadIdx.x == 0) bad = 0;
        __syncthreads();
        const long long* p = (const long long*)ei;
        long long m = (long long)n_elems / 2;
        if (m > 2048) m = 2048;
        for (long long j = threadIdx.x; j < m; j += blockDim.x) {
            long long v = p[j];
            if (v < 0 || v >= N_NODES) bad = 1;
        }
        __syncthreads();
        if (threadIdx.x == 0) g_idx64 = bad ? 0 : 1;
    }
}

__device__ __forceinline__ int load_id(const void* ei, int idx) {
    if (g_idx64) return (int)((const long long*)ei)[idx];
    return ((const int*)ei)[idx];
}

// ---------------- CSR build ----------------
__global__ void k_hist(const void* ei) {
    int e = blockIdx.x * blockDim.x + threadIdx.x;
    if (e >= N_EDGES) return;
    atomicAdd(&g_cnt[load_id(ei, N_EDGES + e)], 1);
}

__device__ __forceinline__ int warp_iscan(int v, int lane) {
    #pragma unroll
    for (int o = 1; o < 32; o <<= 1) {
        int u = __shfl_up_sync(0xffffffffu, v, o);
        if (lane >= o) v += u;
    }
    return v;
}

__global__ void __launch_bounds__(SCAN_BS) k_scan1() {
    int t = threadIdx.x, b = blockIdx.x;
    int i = b * SCAN_BS + t;
    int v = (i < N_NODES) ? g_cnt[i] : 0;
    int lane = t & 31, w = t >> 5;
    __shared__ int ws[SCAN_BS / 32];
    int s = warp_iscan(v, lane);
    if (lane == 31) ws[w] = s;
    __syncthreads();
    if (w == 0) ws[lane] = warp_iscan(ws[lane], lane);
    __syncthreads();
    if (w > 0) s += ws[w - 1];
    if (i < N_NODES) g_inc[i] = s;
    if (t == SCAN_BS - 1) g_bsum[b] = s;
}

__global__ void __launch_bounds__(SCAN_BS) k_scan3() {
    int t = threadIdx.x, b = blockIdx.x;
    __shared__ int pfx;
    if (t < 32) {
        int s = 0;
        for (int i = t; i < b; i += 32) s += g_bsum[i];
        #pragma unroll
        for (int o = 16; o; o >>= 1) s += __shfl_down_sync(0xffffffffu, s, o);
        if (t == 0) pfx = s;
    }
    __syncthreads();
    int i = b * SCAN_BS + t;
    if (i >= N_NODES) return;
    int c = g_cnt[i];
    int off = g_inc[i] - c + pfx;
    g_off[i] = off;
    g_cur[i] = off;
    g_dinv[i] = rsqrtf((float)c + 1.0f);
    if (i == 0) g_off[N_NODES] = N_EDGES;
}

// fill: only src index needed (features pre-scaled by dinv in GEMM epilogues)
__global__ void k_fill(const void* ei) {
    int e = blockIdx.x * blockDim.x + threadIdx.x;
    if (e >= N_EDGES) return;
    int s = load_id(ei, e);
    int d = load_id(ei, N_EDGES + e);
    int pos = atomicAdd(&g_cur[d], 1);
    g_csr[pos] = s * (HID_CH / 2);
}

// ---------------- GEMM1: f1h = fp16((x @ W1) * dinv[row]) ----------------
__global__ void __launch_bounds__(256) k_gemm1(const float* __restrict__ x,
                                               const float* __restrict__ W1) {
    __shared__ float Ws[IN_CH * HID_CH];   // 32KB
    int tid = threadIdx.x;
    {
        const float4* W4 = (const float4*)W1;
        float4* Ws4 = (float4*)Ws;
        #pragma unroll
        for (int i = 0; i < (IN_CH * HID_CH / 4) / 256; i++)
            Ws4[tid + 256 * i] = W4[tid + 256 * i];
    }
    __syncthreads();

    int t    = tid & 7;
    int row0 = blockIdx.x * GEMM_ROWS + (tid >> 3) * 4;
    bool v0 = row0     < N_NODES, v1 = row0 + 1 < N_NODES;
    bool v2 = row0 + 2 < N_NODES, v3 = row0 + 3 < N_NODES;

    u64 acc[4][4];
    #pragma unroll
    for (int r = 0; r < 4; r++)
        #pragma unroll
        for (int j = 0; j < 4; j++) acc[r][j] = 0ull;

    const float4* xr = (const float4*)(x + (size_t)row0 * IN_CH);
    const float4 z4 = make_float4(0.f, 0.f, 0.f, 0.f);

    #pragma unroll 4
    for (int k4 = 0; k4 < IN_CH / 4; k4++) {
        float4 xa0 = v0 ? xr[k4]                    : z4;
        float4 xa1 = v1 ? xr[k4 + IN_CH / 4]        : z4;
        float4 xa2 = v2 ? xr[k4 + 2 * (IN_CH / 4)]  : z4;
        float4 xa3 = v3 ? xr[k4 + 3 * (IN_CH / 4)]  : z4;
        #pragma unroll
        for (int dk = 0; dk < 4; dk++) {
            float s0 = (dk == 0) ? xa0.x : (dk == 1) ? xa0.y : (dk == 2) ? xa0.z : xa0.w;
            float s1 = (dk == 0) ? xa1.x : (dk == 1) ? xa1.y : (dk == 2) ? xa1.z : xa1.w;
            float s2 = (dk == 0) ? xa2.x : (dk == 1) ? xa2.y : (dk == 2) ? xa2.z : xa2.w;
            float s3 = (dk == 0) ? xa3.x : (dk == 1) ? xa3.y : (dk == 2) ? xa3.z : xa3.w;
            u64 xp[4];
            DUP_X2(xp[0], s0); DUP_X2(xp[1], s1);
            DUP_X2(xp[2], s2); DUP_X2(xp[3], s3);
            const u64* wr = (const u64*)&Ws[(k4 * 4 + dk) * HID_CH + t * 8];
            u64 w0 = wr[0], w1 = wr[1], w2 = wr[2], w3 = wr[3];
            #pragma unroll
            for (int r = 0; r < 4; r++) {
                FMA_X2(acc[r][0], xp[r], w0);
                FMA_X2(acc[r][1], xp[r], w1);
                FMA_X2(acc[r][2], xp[r], w2);
                FMA_X2(acc[r][3], xp[r], w3);
            }
        }
    }

    #pragma unroll
    for (int r = 0; r < 4; r++) {
        int row = row0 + r;
        if (row >= N_NODES) break;
        float di = g_dinv[row];
        float a0, a1, a2, a3, a4, a5, a6, a7;
        UNPK_X2(a0, a1, acc[r][0]); UNPK_X2(a2, a3, acc[r][1]);
        UNPK_X2(a4, a5, acc[r][2]); UNPK_X2(a6, a7, acc[r][3]);
        __half2 h0 = __floats2half2_rn(a0 * di, a1 * di);
        __half2 h1 = __floats2half2_rn(a2 * di, a3 * di);
        __half2 h2 = __floats2half2_rn(a4 * di, a5 * di);
        __half2 h3 = __floats2half2_rn(a6 * di, a7 * di);
        uint4 pk = make_uint4(*(uint32_t*)&h0, *(uint32_t*)&h1,
                              *(uint32_t*)&h2, *(uint32_t*)&h3);
        *((uint4*)(g_f1h + (size_t)row * (HID_CH / 2)) + t) = pk;
    }
}

// ---------------- agg layer 1: pure gather-sum + self + bias + relu -> r1 fp32 ----------------
// one warp per node; lane owns channels {2*lane, 2*lane+1}; 4 src records per int4 LDG
__global__ void __launch_bounds__(256) k_agg1(const float* __restrict__ b1) {
    int n = (blockIdx.x * 256 + threadIdx.x) >> 5;
    int lane = threadIdx.x & 31;
    int beg = g_off[n], end = g_off[n + 1];

    float ax = 0.f, ay = 0.f;
    int e = beg;
    while (e < end && (e & 3)) {   // peel to 16B-aligned int4 record loads
        float2 v = __half22float2(g_f1h[g_csr[e] + lane]);
        ax += v.x; ay += v.y;
        e++;
    }
    for (; e + 4 <= end; e += 4) {
        int4 R = *(const int4*)(g_csr + e);
        float2 v0 = __half22float2(g_f1h[R.x + lane]);
        float2 v1 = __half22float2(g_f1h[R.y + lane]);
        float2 v2 = __half22float2(g_f1h[R.z + lane]);
        float2 v3 = __half22float2(g_f1h[R.w + lane]);
        ax += (v0.x + v1.x) + (v2.x + v3.x);
        ay += (v0.y + v1.y) + (v2.y + v3.y);
    }
    for (; e < end; e++) {
        float2 v = __half22float2(g_f1h[g_csr[e] + lane]);
        ax += v.x; ay += v.y;
    }

    float di = g_dinv[n];
    float2 self = __half22float2(g_f1h[(size_t)n * (HID_CH / 2) + lane]);
    float2 bb   = *(const float2*)(b1 + 2 * lane);
    float rx = fmaxf((ax + self.x) * di + bb.x, 0.f);
    float ry = fmaxf((ay + self.y) * di + bb.y, 0.f);
    *(float2*)(g_r1 + (size_t)n * HID_CH + 2 * lane) = make_float2(rx, ry);
}

// ---------------- GEMM2: f2h = fp16((r1 @ W2) * dinv[row]) ----------------
// gemm1's proven shape: 4 col-groups x 8 cols (tid&3), 64 row-groups x 4 rows
// (tid>>2) = 256 rows/block. 16 FMA2 per W-pair per dk -> 2x arithmetic per
// x-byte vs old shape (latency hiding), W smem amortized over 2x rows.
__global__ void __launch_bounds__(256) k_gemm2(const float* __restrict__ W2) {
    __shared__ float Ws[HID_CH * OUT_CH];   // 8KB
    int tid = threadIdx.x;
    {
        const float4* W4 = (const float4*)W2;
        float4* Ws4 = (float4*)Ws;
        #pragma unroll
        for (int i = 0; i < (HID_CH * OUT_CH / 4) / 256; i++)
            Ws4[tid + 256 * i] = W4[tid + 256 * i];
    }
    __syncthreads();

    int t    = tid & 3;                              // 8 output cols
    int row0 = blockIdx.x * GEMM2_ROWS + (tid >> 2) * 4;
    bool v0 = row0     < N_NODES, v1 = row0 + 1 < N_NODES;
    bool v2 = row0 + 2 < N_NODES, v3 = row0 + 3 < N_NODES;

    u64 acc[4][4];
    #pragma unroll
    for (int r = 0; r < 4; r++)
        #pragma unroll
        for (int j = 0; j < 4; j++) acc[r][j] = 0ull;

    const float4* xr = (const float4*)(g_r1 + (size_t)row0 * HID_CH);
    const float4 z4 = make_float4(0.f, 0.f, 0.f, 0.f);

    #pragma unroll 4
    for (int k4 = 0; k4 < HID_CH / 4; k4++) {
        float4 xa0 = v0 ? xr[k4]                     : z4;
        float4 xa1 = v1 ? xr[k4 + HID_CH / 4]        : z4;
        float4 xa2 = v2 ? xr[k4 + 2 * (HID_CH / 4)]  : z4;
        float4 xa3 = v3 ? xr[k4 + 3 * (HID_CH / 4)]  : z4;
        #pragma unroll
        for (int dk = 0; dk < 4; dk++) {
            float s0 = (dk == 0) ? xa0.x : (dk == 1) ? xa0.y : (dk == 2) ? xa0.z : xa0.w;
            float s1 = (dk == 0) ? xa1.x : (dk == 1) ? xa1.y : (dk == 2) ? xa1.z : xa1.w;
            float s2 = (dk == 0) ? xa2.x : (dk == 1) ? xa2.y : (dk == 2) ? xa2.z : xa2.w;
            float s3 = (dk == 0) ? xa3.x : (dk == 1) ? xa3.y : (dk == 2) ? xa3.z : xa3.w;
            u64 xp[4];
            DUP_X2(xp[0], s0); DUP_X2(xp[1], s1);
            DUP_X2(xp[2], s2); DUP_X2(xp[3], s3);
            const u64* wr = (const u64*)&Ws[(k4 * 4 + dk) * OUT_CH + t * 8];
            u64 w0 = wr[0], w1 = wr[1], w2 = wr[2], w3 = wr[3];
            #pragma unroll
            for (int r = 0; r < 4; r++) {
                FMA_X2(acc[r][0], xp[r], w0);
                FMA_X2(acc[r][1], xp[r], w1);
                FMA_X2(acc[r][2], xp[r], w2);
                FMA_X2(acc[r][3], xp[r], w3);
            }
        }
    }

    #pragma unroll
    for (int r = 0; r < 4; r++) {
        int row = row0 + r;
        if (row >= N_NODES) break;
        float di = g_dinv[row];
        float a0, a1, a2, a3, a4, a5, a6, a7;
        UNPK_X2(a0, a1, acc[r][0]); UNPK_X2(a2, a3, acc[r][1]);
        UNPK_X2(a4, a5, acc[r][2]); UNPK_X2(a6, a7, acc[r][3]);
        __half2 h0 = __floats2half2_rn(a0 * di, a1 * di);
        __half2 h1 = __floats2half2_rn(a2 * di, a3 * di);
        __half2 h2 = __floats2half2_rn(a4 * di, a5 * di);
        __half2 h3 = __floats2half2_rn(a6 * di, a7 * di);
        uint4 pk = make_uint4(*(uint32_t*)&h0, *(uint32_t*)&h1,
                              *(uint32_t*)&h2, *(uint32_t*)&h3);
        *((uint4*)(g_f2h + (size_t)row * OUT_CH) + t) = pk;
    }
}

// ---------------- agg layer 2: half-warp edge pairing, pure gather-sum ----------------
// lanes 0-15 take even record slots, 16-31 odd; channel pair c = lane&15; shfl_xor(16) merges.
__global__ void __launch_bounds__(256) k_agg2(const float* __restrict__ b2,
                                              float* __restrict__ out) {
    int n = (blockIdx.x * 256 + threadIdx.x) >> 5;
    int lane = threadIdx.x & 31;
    int half = lane >> 4;
    int c    = lane & 15;
    int beg = g_off[n], end = g_off[n + 1];
    const __half2* f2 = (const __half2*)g_f2h;

    float ax = 0.f, ay = 0.f;
    int e = beg;
    while (e < end && (e & 3)) {   // peel to 16B alignment (half 0 does the work)
        if (half == 0) {
            float2 v = __half22float2(f2[(g_csr[e] >> 1) + c]);
            ax += v.x; ay += v.y;
        }
        e++;
    }
    for (; e + 4 <= end; e += 4) {
        int4 R = *(const int4*)(g_csr + e);
        int r0 = half ? R.y : R.x;
        int r1 = half ? R.w : R.z;
        float2 v0 = __half22float2(f2[(r0 >> 1) + c]);
        float2 v1 = __half22float2(f2[(r1 >> 1) + c]);
        ax += v0.x + v1.x;
        ay += v0.y + v1.y;
    }
    for (; e + 2 <= end; e += 2) {   // tail pairs: each half takes one
        float2 v = __half22float2(f2[(g_csr[e + half] >> 1) + c]);
        ax += v.x; ay += v.y;
    }
    if (e < end && half == 0) {      // final odd edge
        float2 v = __half22float2(f2[(g_csr[e] >> 1) + c]);
        ax += v.x; ay += v.y;
    }

    ax += __shfl_xor_sync(0xffffffffu, ax, 16);
    ay += __shfl_xor_sync(0xffffffffu, ay, 16);

    if (half == 0) {
        float di = g_dinv[n];
        float2 self = __half22float2(f2[(size_t)n * (OUT_CH / 2) + c]);
        float2 bb   = *(const float2*)(b2 + 2 * c);
        *(float2*)(out + (size_t)n * OUT_CH + 2 * c) =
            make_float2((ax + self.x) * di + bb.x, (ay + self.y) * di + bb.y);
    }
}

// ---------------- launch ----------------
extern "C" void kernel_launch(void* const* d_in, const int* in_sizes, int n_in,
                              void* d_out, int out_size) {
    const float* x  = (const float*)d_in[0];
    const void*  ei = d_in[1];
    const float* W1 = (const float*)d_in[2];
    const float* b1 = (const float*)d_in[3];
    const float* W2 = (const float*)d_in[4];
    const float* b2 = (const float*)d_in[5];
    float* out = (float*)d_out;

    k_detect_zero<<<(N_NODES + 255) / 256, 256>>>(ei, in_sizes[1]);
    k_hist <<<N_EDGES / 256, 256>>>(ei);
    k_scan1<<<N_SCAN_BLK, SCAN_BS>>>();
    k_scan3<<<N_SCAN_BLK, SCAN_BS>>>();
    k_fill <<<N_EDGES / 256, 256>>>(ei);

    k_gemm1<<<N_GEMM_BLK, 256>>>(x, W1);
    k_agg1 <<<N_NODES / 8, 256>>>(b1);
    k_gemm2<<<N_GEMM2_BLK, 256>>>(W2);
    k_agg2 <<<N_NODES / 8, 256>>>(b2, out);
}